// round 3
// baseline (speedup 1.0000x reference)
#include <cuda_runtime.h>
#include <math.h>
#include <stdint.h>

#define BB 4
#define SS 512
#define JJ 24
#define HH 128
#define NN 8
#define DD 16
#define FDIM 256

constexpr long long E   = (long long)BB * SS * JJ * HH;
constexpr long long WSZ = (long long)JJ * HH * HH;
constexpr long long WJS = (long long)HH * HH;

constexpr long long OFF_QT   = 0 * E;
constexpr long long OFF_KT   = 1 * E;
constexpr long long OFF_VT   = 2 * E;
constexpr long long OFF_OT   = 3 * E;
constexpr long long OFF_TMP  = 4 * E;
constexpr long long OFF_TOUT = 5 * E;
constexpr long long OFF_QS   = 6 * E;
constexpr long long OFF_KS   = 7 * E;
constexpr long long OFF_VS   = 8 * E;
constexpr long long OFF_OS   = 9 * E;
constexpr long long OFF_SOUT = 10 * E;
constexpr long long OFF_A    = 11 * E;
constexpr long long OFF_FFB  = 12 * E;
constexpr long long OFF_WQT  = 14 * E;
constexpr long long OFF_WKT  = OFF_WQT + 1 * WSZ;
constexpr long long OFF_WVT  = OFF_WQT + 2 * WSZ;
constexpr long long OFF_WQS  = OFF_WQT + 3 * WSZ;
constexpr long long OFF_WKS  = OFF_WQT + 4 * WSZ;
constexpr long long OFF_WVS  = OFF_WKS + (long long)HH * HH;
constexpr long long TOTAL    = OFF_WVS + (long long)HH * HH;

__device__ float g_scratch[TOTAL];

// ---------------------------------------------------------------------------
__global__ void pack_weights(const float* __restrict__ qt, const float* __restrict__ kt,
                             const float* __restrict__ vt, const float* __restrict__ qs,
                             const float* __restrict__ ks, const float* __restrict__ vs,
                             float* __restrict__ g) {
    int idx = blockIdx.x * blockDim.x + threadIdx.x;
    if (idx < (int)WSZ) {
        int j = idx / (HH * HH);
        int h = (idx / HH) % HH;
        int c = idx % HH;
        int n = c / DD, d = c % DD;
        long long src = (((long long)n * JJ + j) * HH + h) * DD + d;
        g[OFF_WQT + idx] = qt[src];
        g[OFF_WKT + idx] = kt[src];
        g[OFF_WVT + idx] = vt[src];
        g[OFF_WQS + idx] = qs[src];
    }
    if (idx < HH * HH) {
        int h = idx / HH, c = idx % HH;
        int n = c / DD, d = c % DD;
        long long src = ((long long)n * HH + h) * DD + d;
        g[OFF_WKS + idx] = ks[src];
        g[OFF_WVS + idx] = vs[src];
    }
}

// ---------------------------------------------------------------------------
// tf32 tensor-core GEMM: C[row][col] = sum_k A[row][k] * W[k][col] (+bias)(+relu)
// BM=128 BN=128 BK=16, 256 threads = 8 warps (2 M x 4 N), warp tile 64x32.
// mma.sync.m16n8k8 tf32. Double-buffered smem, reg-staged gmem prefetch.
// ---------------------------------------------------------------------------
__device__ __forceinline__ uint32_t f2tf(float x) {
    uint32_t u;
    asm("cvt.rna.tf32.f32 %0, %1;" : "=r"(u) : "f"(x));
    return u;
}

__device__ __forceinline__ void mma_tf32(float* d, const uint32_t* a, const uint32_t* b) {
    asm volatile(
        "mma.sync.aligned.m16n8k8.row.col.f32.tf32.tf32.f32 "
        "{%0,%1,%2,%3},{%4,%5,%6,%7},{%8,%9},{%0,%1,%2,%3};"
        : "+f"(d[0]), "+f"(d[1]), "+f"(d[2]), "+f"(d[3])
        : "r"(a[0]), "r"(a[1]), "r"(a[2]), "r"(a[3]), "r"(b[0]), "r"(b[1]));
}

__launch_bounds__(256, 1)
__global__ void gemm_tc(const float* __restrict__ A0, long long aJ, int lda,
                        const float* __restrict__ W0, long long wJ, int ldw,
                        float* __restrict__ C0, long long cJ,
                        int K, int rdiv, long long cHi, long long cLo,
                        const float* __restrict__ bias, int doRelu) {
    __shared__ __align__(16) float As[2][128][20];   // [m][k] stride 20 (frag loads conflict-free)
    __shared__ __align__(16) float Ws[2][16][136];   // [k][n] stride 136 (frag loads conflict-free)

    int j  = blockIdx.y;
    int zt = blockIdx.z;
    const float* A = A0 + (long long)j * aJ;
    const float* W = W0 + (long long)j * wJ + zt * 128;
    int row0 = blockIdx.x * 128;
    int tid  = threadIdx.x;
    int lane = tid & 31, wid = tid >> 5;
    int wm = (wid & 1) * 64;
    int wn = (wid >> 1) * 32;
    int grp = lane >> 2, tg = lane & 3;

    // gmem->reg staging indices
    int ar = tid >> 1;              // A row 0..127
    int ak = (tid & 1) * 8;         // A k offset 0/8
    int bk = tid >> 4;              // W k row 0..15
    int bc = (tid & 15) * 4;        // W col 0..60

    float acc[4][4][4];
#pragma unroll
    for (int mm = 0; mm < 4; mm++)
#pragma unroll
        for (int nn = 0; nn < 4; nn++)
#pragma unroll
            for (int q = 0; q < 4; q++) acc[mm][nn][q] = 0.f;

    float4 ra0, ra1, rb0, rb1;

    const long long arow = (long long)(row0 + ar) * lda;

    // tile 0
    ra0 = *(const float4*)(A + arow + 0 + ak);
    ra1 = *(const float4*)(A + arow + 0 + ak + 4);
    rb0 = *(const float4*)(W + (long long)(0 + bk) * ldw + bc);
    rb1 = *(const float4*)(W + (long long)(0 + bk) * ldw + bc + 64);
    {
        As[0][ar][ak + 0] = __uint_as_float(f2tf(ra0.x));
        As[0][ar][ak + 1] = __uint_as_float(f2tf(ra0.y));
        As[0][ar][ak + 2] = __uint_as_float(f2tf(ra0.z));
        As[0][ar][ak + 3] = __uint_as_float(f2tf(ra0.w));
        As[0][ar][ak + 4] = __uint_as_float(f2tf(ra1.x));
        As[0][ar][ak + 5] = __uint_as_float(f2tf(ra1.y));
        As[0][ar][ak + 6] = __uint_as_float(f2tf(ra1.z));
        As[0][ar][ak + 7] = __uint_as_float(f2tf(ra1.w));
        float4 c0 = make_float4(__uint_as_float(f2tf(rb0.x)), __uint_as_float(f2tf(rb0.y)),
                                __uint_as_float(f2tf(rb0.z)), __uint_as_float(f2tf(rb0.w)));
        float4 c1 = make_float4(__uint_as_float(f2tf(rb1.x)), __uint_as_float(f2tf(rb1.y)),
                                __uint_as_float(f2tf(rb1.z)), __uint_as_float(f2tf(rb1.w)));
        *(float4*)&Ws[0][bk][bc]      = c0;
        *(float4*)&Ws[0][bk][bc + 64] = c1;
    }
    __syncthreads();

    int nt = K / 16;
    for (int t = 0; t < nt; t++) {
        int cur = t & 1;
        if (t + 1 < nt) {
            int k0 = (t + 1) * 16;
            ra0 = *(const float4*)(A + arow + k0 + ak);
            ra1 = *(const float4*)(A + arow + k0 + ak + 4);
            rb0 = *(const float4*)(W + (long long)(k0 + bk) * ldw + bc);
            rb1 = *(const float4*)(W + (long long)(k0 + bk) * ldw + bc + 64);
        }
        // compute on buffer cur
#pragma unroll
        for (int ks = 0; ks < 2; ks++) {
            int kk = ks * 8 + tg;
            uint32_t af[4][4];
#pragma unroll
            for (int mm = 0; mm < 4; mm++) {
                int m = wm + mm * 16 + grp;
                af[mm][0] = __float_as_uint(As[cur][m][kk]);
                af[mm][1] = __float_as_uint(As[cur][m + 8][kk]);
                af[mm][2] = __float_as_uint(As[cur][m][kk + 4]);
                af[mm][3] = __float_as_uint(As[cur][m + 8][kk + 4]);
            }
            uint32_t bf[4][2];
#pragma unroll
            for (int nn = 0; nn < 4; nn++) {
                int n = wn + nn * 8 + grp;
                bf[nn][0] = __float_as_uint(Ws[cur][kk][n]);
                bf[nn][1] = __float_as_uint(Ws[cur][kk + 4][n]);
            }
#pragma unroll
            for (int mm = 0; mm < 4; mm++)
#pragma unroll
                for (int nn = 0; nn < 4; nn++)
                    mma_tf32(acc[mm][nn], af[mm], bf[nn]);
        }
        if (t + 1 < nt) {
            int nb = 1 - cur;
            As[nb][ar][ak + 0] = __uint_as_float(f2tf(ra0.x));
            As[nb][ar][ak + 1] = __uint_as_float(f2tf(ra0.y));
            As[nb][ar][ak + 2] = __uint_as_float(f2tf(ra0.z));
            As[nb][ar][ak + 3] = __uint_as_float(f2tf(ra0.w));
            As[nb][ar][ak + 4] = __uint_as_float(f2tf(ra1.x));
            As[nb][ar][ak + 5] = __uint_as_float(f2tf(ra1.y));
            As[nb][ar][ak + 6] = __uint_as_float(f2tf(ra1.z));
            As[nb][ar][ak + 7] = __uint_as_float(f2tf(ra1.w));
            float4 c0 = make_float4(__uint_as_float(f2tf(rb0.x)), __uint_as_float(f2tf(rb0.y)),
                                    __uint_as_float(f2tf(rb0.z)), __uint_as_float(f2tf(rb0.w)));
            float4 c1 = make_float4(__uint_as_float(f2tf(rb1.x)), __uint_as_float(f2tf(rb1.y)),
                                    __uint_as_float(f2tf(rb1.z)), __uint_as_float(f2tf(rb1.w)));
            *(float4*)&Ws[nb][bk][bc]      = c0;
            *(float4*)&Ws[nb][bk][bc + 64] = c1;
        }
        __syncthreads();
    }

    // epilogue
#pragma unroll
    for (int mm = 0; mm < 4; mm++) {
#pragma unroll
        for (int half = 0; half < 2; half++) {
            int r = row0 + wm + mm * 16 + grp + half * 8;
            float* Cr = C0 + (long long)j * cJ + (long long)(r / rdiv) * cHi +
                        (long long)(r % rdiv) * cLo + (long long)zt * 128;
#pragma unroll
            for (int nn = 0; nn < 4; nn++) {
                int c = wn + nn * 8 + tg * 2;
                float v0 = acc[mm][nn][half * 2 + 0];
                float v1 = acc[mm][nn][half * 2 + 1];
                if (bias) {
                    v0 += bias[zt * 128 + c];
                    v1 += bias[zt * 128 + c + 1];
                }
                if (doRelu) { v0 = fmaxf(v0, 0.f); v1 = fmaxf(v1, 0.f); }
                *(float2*)&Cr[c] = make_float2(v0, v1);
            }
        }
    }
}

// ---------------------------------------------------------------------------
// Temporal causal attention: one block per (b,j,n), 256 threads, 2 rows/thread.
// Two-phase loop: t<=s0 both rows (no predicate), then (s0,s1] row1 only.
// ---------------------------------------------------------------------------
__global__ void temporal_attn(const float* __restrict__ Q, const float* __restrict__ Kt,
                              const float* __restrict__ V, float* __restrict__ O) {
    extern __shared__ float sm[];
    float* Ksm = sm;
    float* Vsm = sm + SS * DD;

    int n  = blockIdx.y;
    int bj = blockIdx.z;
    int b = bj / JJ, j = bj % JJ;
    long long base = (long long)bj * SS * HH;
    int tid = threadIdx.x;
    int co = n * 16;

    for (int i = tid; i < SS * DD / 4; i += 256) {
        int t = i >> 2, dq = i & 3;
        *(float4*)&Ksm[t * 16 + dq * 4] = *(const float4*)&Kt[base + (long long)t * HH + co + dq * 4];
        *(float4*)&Vsm[t * 16 + dq * 4] = *(const float4*)&V[base + (long long)t * HH + co + dq * 4];
    }
    __syncthreads();

    int s0 = tid, s1 = tid + 256;
    float q0[16], q1[16];
#pragma unroll
    for (int dq = 0; dq < 4; dq++) {
        *(float4*)&q0[dq * 4] = *(const float4*)&Q[base + (long long)s0 * HH + co + dq * 4];
        *(float4*)&q1[dq * 4] = *(const float4*)&Q[base + (long long)s1 * HH + co + dq * 4];
    }
    float o0[16], o1[16];
#pragma unroll
    for (int d = 0; d < 16; d++) { o0[d] = 0.f; o1[d] = 0.f; }
    float m0 = -1e30f, m1 = -1e30f, l0 = 0.f, l1 = 0.f;

    // phase 1: t <= s0, both rows active
    for (int t = 0; t <= s0; t++) {
        float kf[16], vf[16];
#pragma unroll
        for (int dq = 0; dq < 4; dq++) {
            *(float4*)&kf[dq * 4] = *(const float4*)&Ksm[t * 16 + dq * 4];
            *(float4*)&vf[dq * 4] = *(const float4*)&Vsm[t * 16 + dq * 4];
        }
        {
            float a0 = 0, a1 = 0, a2 = 0, a3 = 0;
#pragma unroll
            for (int d = 0; d < 16; d += 4) {
                a0 += q1[d] * kf[d];     a1 += q1[d + 1] * kf[d + 1];
                a2 += q1[d + 2] * kf[d + 2]; a3 += q1[d + 3] * kf[d + 3];
            }
            float sc = ((a0 + a1) + (a2 + a3)) * 0.25f;
            if (sc > m1) {
                float corr = __expf(m1 - sc);
                l1 = l1 * corr + 1.f;
#pragma unroll
                for (int d = 0; d < 16; d++) o1[d] = o1[d] * corr + vf[d];
                m1 = sc;
            } else {
                float p = __expf(sc - m1);
                l1 += p;
#pragma unroll
                for (int d = 0; d < 16; d++) o1[d] += p * vf[d];
            }
        }
        {
            float a0 = 0, a1 = 0, a2 = 0, a3 = 0;
#pragma unroll
            for (int d = 0; d < 16; d += 4) {
                a0 += q0[d] * kf[d];     a1 += q0[d + 1] * kf[d + 1];
                a2 += q0[d + 2] * kf[d + 2]; a3 += q0[d + 3] * kf[d + 3];
            }
            float sc = ((a0 + a1) + (a2 + a3)) * 0.25f;
            if (sc > m0) {
                float corr = __expf(m0 - sc);
                l0 = l0 * corr + 1.f;
#pragma unroll
                for (int d = 0; d < 16; d++) o0[d] = o0[d] * corr + vf[d];
                m0 = sc;
            } else {
                float p = __expf(sc - m0);
                l0 += p;
#pragma unroll
                for (int d = 0; d < 16; d++) o0[d] += p * vf[d];
            }
        }
    }
    // phase 2: s0 < t <= s1, row1 only
    for (int t = s0 + 1; t <= s1; t++) {
        float kf[16], vf[16];
#pragma unroll
        for (int dq = 0; dq < 4; dq++) {
            *(float4*)&kf[dq * 4] = *(const float4*)&Ksm[t * 16 + dq * 4];
            *(float4*)&vf[dq * 4] = *(const float4*)&Vsm[t * 16 + dq * 4];
        }
        float a0 = 0, a1 = 0, a2 = 0, a3 = 0;
#pragma unroll
        for (int d = 0; d < 16; d += 4) {
            a0 += q1[d] * kf[d];     a1 += q1[d + 1] * kf[d + 1];
            a2 += q1[d + 2] * kf[d + 2]; a3 += q1[d + 3] * kf[d + 3];
        }
        float sc = ((a0 + a1) + (a2 + a3)) * 0.25f;
        if (sc > m1) {
            float corr = __expf(m1 - sc);
            l1 = l1 * corr + 1.f;
#pragma unroll
            for (int d = 0; d < 16; d++) o1[d] = o1[d] * corr + vf[d];
            m1 = sc;
        } else {
            float p = __expf(sc - m1);
            l1 += p;
#pragma unroll
            for (int d = 0; d < 16; d++) o1[d] += p * vf[d];
        }
    }

    float i0 = 1.f / l0, i1 = 1.f / l1;
    long long ob0 = ((long long)(b * SS + s0) * JJ + j) * HH + co;
    long long ob1 = ((long long)(b * SS + s1) * JJ + j) * HH + co;
#pragma unroll
    for (int dq = 0; dq < 4; dq++) {
        *(float4*)&O[ob0 + dq * 4] = make_float4(o0[dq * 4] * i0, o0[dq * 4 + 1] * i0,
                                                 o0[dq * 4 + 2] * i0, o0[dq * 4 + 3] * i0);
        *(float4*)&O[ob1 + dq * 4] = make_float4(o1[dq * 4] * i1, o1[dq * 4 + 1] * i1,
                                                 o1[dq * 4 + 2] * i1, o1[dq * 4 + 3] * i1);
    }
}

// ---------------------------------------------------------------------------
__global__ void spatial_attn(const float* __restrict__ Q, const float* __restrict__ K,
                             const float* __restrict__ V, float* __restrict__ O) {
    __shared__ float Qs[JJ * HH], Ks[JJ * HH], Vs[JJ * HH];
    long long base = (long long)blockIdx.x * JJ * HH;
    int tid = threadIdx.x;
    for (int i = tid; i < JJ * HH / 4; i += 256) {
        ((float4*)Qs)[i] = ((const float4*)(Q + base))[i];
        ((float4*)Ks)[i] = ((const float4*)(K + base))[i];
        ((float4*)Vs)[i] = ((const float4*)(V + base))[i];
    }
    __syncthreads();
    if (tid < NN * JJ) {
        int n = tid / JJ, jq = tid % JJ;
        int co = n * 16;
        float q[16];
#pragma unroll
        for (int d = 0; d < 16; d++) q[d] = Qs[jq * HH + co + d];
        float sc[JJ];
        float mx = -1e30f;
#pragma unroll
        for (int k = 0; k < JJ; k++) {
            float s = 0.f;
#pragma unroll
            for (int d = 0; d < 16; d++) s += q[d] * Ks[k * HH + co + d];
            s *= 0.25f;
            sc[k] = s;
            mx = fmaxf(mx, s);
        }
        float l = 0.f;
#pragma unroll
        for (int k = 0; k < JJ; k++) {
            float p = __expf(sc[k] - mx);
            sc[k] = p;
            l += p;
        }
        float o[16];
#pragma unroll
        for (int d = 0; d < 16; d++) o[d] = 0.f;
#pragma unroll
        for (int k = 0; k < JJ; k++)
#pragma unroll
            for (int d = 0; d < 16; d++) o[d] += sc[k] * Vs[k * HH + co + d];
        float inv = 1.f / l;
#pragma unroll
        for (int d = 0; d < 16; d++) O[base + jq * HH + co + d] = o[d] * inv;
    }
}

// ---------------------------------------------------------------------------
__global__ void ln_residual(const float* __restrict__ A, const float* __restrict__ B,
                            const float* __restrict__ w, const float* __restrict__ bb,
                            float* __restrict__ out) {
    int row  = blockIdx.x * 8 + (threadIdx.x >> 5);
    int lane = threadIdx.x & 31;
    long long off = (long long)row * HH + lane * 4;
    float4 va = *(const float4*)(A + off);
    float4 vb = *(const float4*)(B + off);
    float v0 = va.x + vb.x, v1 = va.y + vb.y, v2 = va.z + vb.z, v3 = va.w + vb.w;
    float s = v0 + v1 + v2 + v3;
#pragma unroll
    for (int o_ = 16; o_ > 0; o_ >>= 1) s += __shfl_xor_sync(0xffffffffu, s, o_);
    float mu = s * 0.0078125f;
    float d0 = v0 - mu, d1 = v1 - mu, d2 = v2 - mu, d3 = v3 - mu;
    float sq = d0 * d0 + d1 * d1 + d2 * d2 + d3 * d3;
#pragma unroll
    for (int o_ = 16; o_ > 0; o_ >>= 1) sq += __shfl_xor_sync(0xffffffffu, sq, o_);
    float rstd = rsqrtf(sq * 0.0078125f + 1e-5f);
    float4 wv = *(const float4*)(w + lane * 4);
    float4 bv = *(const float4*)(bb + lane * 4);
    float4 r;
    r.x = d0 * rstd * wv.x + bv.x;
    r.y = d1 * rstd * wv.y + bv.y;
    r.z = d2 * rstd * wv.z + bv.z;
    r.w = d3 * rstd * wv.w + bv.w;
    *(float4*)(out + off) = r;
}

__global__ void add2(const float* __restrict__ a, const float* __restrict__ b,
                     float* __restrict__ c) {
    long long i = (long long)blockIdx.x * blockDim.x + threadIdx.x;
    float4 va = ((const float4*)a)[i];
    float4 vb = ((const float4*)b)[i];
    ((float4*)c)[i] = make_float4(va.x + vb.x, va.y + vb.y, va.z + vb.z, va.w + vb.w);
}

// ---------------------------------------------------------------------------
extern "C" void kernel_launch(void* const* d_in, const int* in_sizes, int n_in,
                              void* d_out, int out_size) {
    const float* x        = (const float*)d_in[0];
    const float* q_t      = (const float*)d_in[2];
    const float* k_t      = (const float*)d_in[3];
    const float* v_t      = (const float*)d_in[4];
    const float* proj_t   = (const float*)d_in[5];
    const float* ln_t_w   = (const float*)d_in[6];
    const float* ln_t_b   = (const float*)d_in[7];
    const float* q_s      = (const float*)d_in[8];
    const float* k_s      = (const float*)d_in[9];
    const float* v_s      = (const float*)d_in[10];
    const float* proj_s_w = (const float*)d_in[11];
    const float* proj_s_b = (const float*)d_in[12];
    const float* ln_s_w   = (const float*)d_in[13];
    const float* ln_s_b   = (const float*)d_in[14];
    const float* ff1_w    = (const float*)d_in[15];
    const float* ff1_b    = (const float*)d_in[16];
    const float* ff2_w    = (const float*)d_in[17];
    const float* ff2_b    = (const float*)d_in[18];
    const float* ln_f_w   = (const float*)d_in[19];
    const float* ln_f_b   = (const float*)d_in[20];
    float* out = (float*)d_out;

    float* g = nullptr;
    cudaGetSymbolAddress((void**)&g, g_scratch);

    const int BIG = 1 << 30;
    const long long cHiT = (long long)JJ * SS * HH;
    const long long cJT  = (long long)SS * HH;

    pack_weights<<<(int)((WSZ + 255) / 256), 256>>>(q_t, k_t, v_t, q_s, k_s, v_s, g);

    // 1. temporal qkv: per-j GEMM, out [b][j][s][c]
    dim3 gT(SS * BB / 128, JJ, 1);
    gemm_tc<<<gT, 256>>>(x, HH, JJ * HH, g + OFF_WQT, WJS, HH,
                         g + OFF_QT, cJT, HH, SS, cHiT, HH, nullptr, 0);
    gemm_tc<<<gT, 256>>>(x, HH, JJ * HH, g + OFF_WKT, WJS, HH,
                         g + OFF_KT, cJT, HH, SS, cHiT, HH, nullptr, 0);
    gemm_tc<<<gT, 256>>>(x, HH, JJ * HH, g + OFF_WVT, WJS, HH,
                         g + OFF_VT, cJT, HH, SS, cHiT, HH, nullptr, 0);

    // 2. temporal attention
    cudaFuncSetAttribute(temporal_attn, cudaFuncAttributeMaxDynamicSharedMemorySize, 65536);
    dim3 gA(1, NN, BB * JJ);
    temporal_attn<<<gA, 256, 65536>>>(g + OFF_QT, g + OFF_KT, g + OFF_VT, g + OFF_OT);

    // 3. temporal proj -> tmp, LN(+x) -> tout
    gemm_tc<<<gT, 256>>>(g + OFF_OT, HH, JJ * HH, proj_t, (long long)HH * HH, HH,
                         g + OFF_TMP, HH, HH, BIG, 0, (long long)JJ * HH, nullptr, 0);
    ln_residual<<<BB * SS * JJ / 8, 256>>>(g + OFF_TMP, x, ln_t_w, ln_t_b, g + OFF_TOUT);

    // 4. spatial qkv
    gemm_tc<<<gT, 256>>>(x, HH, JJ * HH, g + OFF_WQS, WJS, HH,
                         g + OFF_QS, HH, HH, BIG, 0, (long long)JJ * HH, nullptr, 0);
    dim3 gF(BB * SS * JJ / 128, 1, 1);
    gemm_tc<<<gF, 256>>>(x, 0, HH, g + OFF_WKS, 0, HH,
                         g + OFF_KS, 0, HH, BIG, 0, HH, nullptr, 0);
    gemm_tc<<<gF, 256>>>(x, 0, HH, g + OFF_WVS, 0, HH,
                         g + OFF_VS, 0, HH, BIG, 0, HH, nullptr, 0);

    // 5. spatial attention
    spatial_attn<<<BB * SS, 256>>>(g + OFF_QS, g + OFF_KS, g + OFF_VS, g + OFF_OS);

    // 6. spatial proj + bias -> tmp, LN(+x) -> sout
    gemm_tc<<<gF, 256>>>(g + OFF_OS, 0, HH, proj_s_w, 0, HH,
                         g + OFF_TMP, 0, HH, BIG, 0, HH, proj_s_b, 0);
    ln_residual<<<BB * SS * JJ / 8, 256>>>(g + OFF_TMP, x, ln_s_w, ln_s_b, g + OFF_SOUT);

    // 7. a = t_out + s_out
    add2<<<(int)(E / 4 / 256), 256>>>(g + OFF_TOUT, g + OFF_SOUT, g + OFF_A);

    // 8. ff1 (+bias, relu)
    dim3 gFF(BB * SS * JJ / 128, 1, 2);
    gemm_tc<<<gFF, 256>>>(g + OFF_A, 0, HH, ff1_w, 0, FDIM,
                          g + OFF_FFB, 0, HH, BIG, 0, FDIM, ff1_b, 1);

    // 9. ff2 (+bias) K=256 -> tmp, final LN(a + ff) -> out
    gemm_tc<<<gF, 256>>>(g + OFF_FFB, 0, FDIM, ff2_w, 0, HH,
                         g + OFF_TMP, 0, FDIM, BIG, 0, HH, ff2_b, 0);
    ln_residual<<<BB * SS * JJ / 8, 256>>>(g + OFF_A, g + OFF_TMP, ln_f_w, ln_f_b, out);
}